// round 1
// baseline (speedup 1.0000x reference)
#include <cuda_runtime.h>
#include <cuda_bf16.h>

// ---------------- problem constants ----------------
#define NB 16
#define NC 32
#define NH 192
#define NW 192
#define NE 8
#define HWSZ (NH*NW)            // 36864
#define GCH 128                 // 4 basis * 32 channels
#define YELEMS ((size_t)NB*NC*NH*NW)

// tile config for the conv kernel
#define TH 8
#define TW 32
#define THREADS 256
#define GPITCH 35               // (TW+2)=34 padded to 35 -> conflict-free
#define GPLANE (10*GPITCH)      // (TH+2) rows * pitch = 350 floats per g-plane
#define NPLANES 16              // 4 x-channels * 4 basis per chunk
#define NCHUNKS 8
#define WS_ULL (16*9*32)        // 4608 duplicated weights per chunk
#define SMEM_BYTES (NPLANES*GPLANE*4 + WS_ULL*8)   // 22400 + 36864 = 59264

// ---------------- device globals (scratch; no allocs allowed) ----------------
__device__ float g_gate[NB*NC];
__device__ float g_scale[NB];
__device__ __align__(16) unsigned long long g_wdup[NCHUNKS*WS_ULL]; // 294912 B

// ---------------- helpers ----------------
__device__ __forceinline__ unsigned long long pack2(float lo, float hi) {
    unsigned long long r;
    asm("mov.b64 %0, {%1, %2};" : "=l"(r) : "f"(lo), "f"(hi));
    return r;
}
__device__ __forceinline__ void unpack2(unsigned long long v, float& lo, float& hi) {
    asm("mov.b64 {%0, %1}, %2;" : "=f"(lo), "=f"(hi) : "l"(v));
}
__device__ __forceinline__ void fma2(unsigned long long& d, unsigned long long a, unsigned long long b) {
    asm("fma.rn.f32x2 %0, %1, %2, %3;" : "=l"(d) : "l"(a), "l"(b), "l"(d));
}
__device__ __forceinline__ float silu_f(float z) {
    float e = __expf(-z);
    return __fdividef(z, 1.0f + e);
}

// ---------------- kernel 1: gate_x = mean(x, H, W) ----------------
__global__ void k_gate_mean(const float* __restrict__ x) {
    int plane = blockIdx.x;                    // 0..511 == n*32 + c
    const float* p = x + (size_t)plane * HWSZ;
    float s = 0.f;
    for (int i = threadIdx.x; i < HWSZ; i += 256) s += p[i];
    __shared__ float red[256];
    red[threadIdx.x] = s;
    __syncthreads();
    for (int off = 128; off > 0; off >>= 1) {
        if (threadIdx.x < off) red[threadIdx.x] += red[threadIdx.x + off];
        __syncthreads();
    }
    if (threadIdx.x == 0) g_gate[plane] = red[0] * (1.0f / (float)HWSZ);
}

// ---------------- kernel 2: gating (softmax, top-2, scale, loss) ----------------
__device__ __forceinline__ float cv2_8(const float* v) {
    float m = 0.f;
    for (int i = 0; i < 8; ++i) m += v[i];
    m *= 0.125f;
    float var = 0.f;
    for (int i = 0; i < 8; ++i) { float d = v[i] - m; var += d * d; }
    var *= (1.0f / 7.0f);       // ddof=1
    return var / (m * m + 1e-10f);
}

__global__ void k_gating(const float* __restrict__ wg, float* __restrict__ loss_out) {
    __shared__ float sgates[NB][NE];
    int n = threadIdx.x;
    if (n < NB) {
        float logit[NE];
        #pragma unroll
        for (int e = 0; e < NE; ++e) logit[e] = 0.f;
        for (int c = 0; c < NC; ++c) {
            float gx = g_gate[n * NC + c];
            #pragma unroll
            for (int e = 0; e < NE; ++e) logit[e] += gx * wg[c * NE + e];
        }
        float mx = logit[0];
        #pragma unroll
        for (int e = 1; e < NE; ++e) mx = fmaxf(mx, logit[e]);
        float pr[NE]; float se = 0.f;
        #pragma unroll
        for (int e = 0; e < NE; ++e) { pr[e] = __expf(logit[e] - mx); se += pr[e]; }
        float inv = 1.0f / se;
        #pragma unroll
        for (int e = 0; e < NE; ++e) pr[e] *= inv;
        // top-2
        int i0 = 0;
        #pragma unroll
        for (int e = 1; e < NE; ++e) if (pr[e] > pr[i0]) i0 = e;
        int i1 = (i0 == 0) ? 1 : 0;
        #pragma unroll
        for (int e = 0; e < NE; ++e) if (e != i0 && pr[e] > pr[i1]) i1 = e;
        float v0 = pr[i0], v1 = pr[i1];
        float denom = v0 + v1 + 1e-6f;
        #pragma unroll
        for (int e = 0; e < NE; ++e) sgates[n][e] = 0.f;
        sgates[n][i0] = v0 / denom;
        sgates[n][i1] = v1 / denom;
        g_scale[n] = (v0 + v1) / denom;
    }
    __syncthreads();
    if (threadIdx.x == 0) {
        float imp[NE], ld[NE];
        #pragma unroll
        for (int e = 0; e < NE; ++e) { imp[e] = 0.f; ld[e] = 0.f; }
        for (int b = 0; b < NB; ++b)
            for (int e = 0; e < NE; ++e) {
                float v = sgates[b][e];
                imp[e] += v;
                if (v > 0.f) ld[e] += 1.f;
            }
        *loss_out = 0.01f * (cv2_8(imp) + cv2_8(ld));
    }
}

// ---------------- kernel 3: duplicated weight layout [cb][ch][k][o] ----------------
// ch = c4*4 + b, global g-channel gi = b*32 + cb*4 + c4
__global__ void k_wdup(const float* __restrict__ pw) {
    int idx = blockIdx.x * 256 + threadIdx.x;       // < 36864
    int o  = idx & 31;
    int k  = (idx >> 5) % 9;
    int t  = (idx >> 5) / 9;                        // cb*16 + ch
    int ch = t & 15;
    int cb = t >> 4;
    int b  = ch & 3;
    int c4 = ch >> 2;
    int gi = b * 32 + cb * 4 + c4;
    float w = pw[(size_t)o * (GCH * 9) + gi * 9 + k];
    g_wdup[idx] = pack2(w, w);
}

// ---------------- kernel 4: fused gram-basis + conv + per-batch scale ----------------
__global__ void __launch_bounds__(THREADS, 2)
k_moe_conv(const float* __restrict__ x, const float* __restrict__ betaw,
           float* __restrict__ y) {
    extern __shared__ float smem[];
    float* gs = smem;                                          // NPLANES * GPLANE floats
    unsigned long long* ws = (unsigned long long*)(smem + NPLANES * GPLANE);

    const int n  = blockIdx.z;
    const int y0 = blockIdx.y * TH;
    const int x0 = blockIdx.x * TW;
    const int tid = threadIdx.x;
    const int og  = tid >> 6;          // 0..3 (out-channel group of 8)
    const int pt  = tid & 63;
    const int row = pt >> 3;           // 0..7
    const int q   = pt & 7;            // 0..7
    const int col0 = q * 4;
    const int og8  = og * 8;

    const float B2 = 2.25f * betaw[1];
    const float B3 = (100.0f / 3.0f) * betaw[2];
    const float G0 = 0.7310585786300049f;   // silu(1)

    unsigned long long acc[16];
    #pragma unroll
    for (int i = 0; i < 16; ++i) acc[i] = 0ull;

    const float* xn = x + (size_t)n * NC * HWSZ;

    for (int cb = 0; cb < NCHUNKS; ++cb) {
        __syncthreads();
        // ---- stage duplicated weights for this chunk (plain contiguous copy) ----
        {
            const uint4* src = (const uint4*)(g_wdup + cb * WS_ULL);
            uint4* dst = (uint4*)ws;
            #pragma unroll
            for (int i = 0; i < WS_ULL / 2 / THREADS; ++i)
                dst[tid + i * THREADS] = src[tid + i * THREADS];
        }
        // ---- stage g tile: 4 x-channels x (TH+2) rows x 34 cols ----
        for (int idx = tid; idx < 4 * 10 * 34; idx += THREADS) {
            int c4  = idx / 340;
            int rem = idx - c4 * 340;
            int r   = rem / 34;
            int cc  = rem - r * 34;
            int gy = y0 - 1 + r;
            int gx = x0 - 1 + cc;
            float g0, g1, g2, g3;
            if ((unsigned)gy < (unsigned)NH && (unsigned)gx < (unsigned)NW) {
                float xv = xn[(size_t)(cb * 4 + c4) * HWSZ + gy * NW + gx];
                float t  = tanhf(xv);
                float P2 = t * t - B2;
                float P3 = t * P2 - B3 * t;
                g0 = G0;
                g1 = silu_f(t);
                g2 = silu_f(P2);
                g3 = silu_f(P3);
            } else {
                g0 = g1 = g2 = g3 = 0.f;
            }
            int base = r * GPITCH + cc;
            gs[(c4 * 4 + 0) * GPLANE + base] = g0;
            gs[(c4 * 4 + 1) * GPLANE + base] = g1;
            gs[(c4 * 4 + 2) * GPLANE + base] = g2;
            gs[(c4 * 4 + 3) * GPLANE + base] = g3;
        }
        __syncthreads();
        // ---- register-tiled f32x2 GEMM over this chunk's 16 g-planes x 9 taps ----
        #pragma unroll 1
        for (int ch = 0; ch < NPLANES; ++ch) {
            const unsigned long long* wp = ws + ch * (9 * 32) + og8;
            const float* gb = gs + ch * GPLANE + row * GPITCH + col0;
            #pragma unroll
            for (int ky = 0; ky < 3; ++ky) {
                const float* gr = gb + ky * GPITCH;
                float a0 = gr[0], a1 = gr[1], a2 = gr[2],
                      a3 = gr[3], a4 = gr[4], a5 = gr[5];
                unsigned long long p01 = pack2(a0, a1);
                unsigned long long p12 = pack2(a1, a2);
                unsigned long long p23 = pack2(a2, a3);
                unsigned long long p34 = pack2(a3, a4);
                unsigned long long p45 = pack2(a4, a5);
                #pragma unroll
                for (int kx = 0; kx < 3; ++kx) {
                    unsigned long long gA = (kx == 0) ? p01 : (kx == 1) ? p12 : p23;
                    unsigned long long gB = (kx == 0) ? p23 : (kx == 1) ? p34 : p45;
                    const unsigned long long* w = wp + (ky * 3 + kx) * 32;
                    ulonglong2 w01 = *(const ulonglong2*)(w + 0);
                    ulonglong2 w23 = *(const ulonglong2*)(w + 2);
                    ulonglong2 w45 = *(const ulonglong2*)(w + 4);
                    ulonglong2 w67 = *(const ulonglong2*)(w + 6);
                    fma2(acc[0],  w01.x, gA); fma2(acc[1],  w01.x, gB);
                    fma2(acc[2],  w01.y, gA); fma2(acc[3],  w01.y, gB);
                    fma2(acc[4],  w23.x, gA); fma2(acc[5],  w23.x, gB);
                    fma2(acc[6],  w23.y, gA); fma2(acc[7],  w23.y, gB);
                    fma2(acc[8],  w45.x, gA); fma2(acc[9],  w45.x, gB);
                    fma2(acc[10], w45.y, gA); fma2(acc[11], w45.y, gB);
                    fma2(acc[12], w67.x, gA); fma2(acc[13], w67.x, gB);
                    fma2(acc[14], w67.y, gA); fma2(acc[15], w67.y, gB);
                }
            }
        }
    }

    // ---- epilogue: scale by per-batch gate sum and store ----
    float s = g_scale[n];
    int gy = y0 + row;
    #pragma unroll
    for (int o = 0; o < 8; ++o) {
        float lo0, hi0, lo1, hi1;
        unpack2(acc[2 * o],     lo0, hi0);
        unpack2(acc[2 * o + 1], lo1, hi1);
        float4 v;
        v.x = lo0 * s; v.y = hi0 * s; v.z = lo1 * s; v.w = hi1 * s;
        size_t off = ((size_t)(n * NC + og8 + o) * NH + gy) * NW + x0 + col0;
        *(float4*)(y + off) = v;
    }
}

// ---------------- launcher ----------------
extern "C" void kernel_launch(void* const* d_in, const int* in_sizes, int n_in,
                              void* d_out, int out_size) {
    const float* x  = (const float*)d_in[0];
    const float* wg = (const float*)d_in[1];
    const float* pw = (const float*)d_in[2];
    const float* bw = (const float*)d_in[3];
    float* out = (float*)d_out;

    cudaFuncSetAttribute(k_moe_conv, cudaFuncAttributeMaxDynamicSharedMemorySize, SMEM_BYTES);

    k_gate_mean<<<NB * NC, 256>>>(x);
    k_gating<<<1, 32>>>(wg, out + (out_size - 1));
    k_wdup<<<144, 256>>>(pw);
    dim3 grid(NW / TW, NH / TH, NB);
    k_moe_conv<<<grid, THREADS, SMEM_BYTES>>>(x, bw, out);
}

// round 2
// speedup vs baseline: 2.2595x; 2.2595x over previous
#include <cuda_runtime.h>
#include <cuda_bf16.h>

// ---------------- problem constants ----------------
#define NB 16
#define NC 32
#define NH 192
#define NW 192
#define NE 8
#define HWSZ (NH*NW)

// conv tile config: 8 rows x 64 cols per block, 32 outs
// thread: og (0..3) x 8 outs, pt (0..63): row=pt>>3, q=pt&7
// pixels per thread: 8 = two 4-wide halves at col0=q*4 and col0+32
#define TH 8
#define TW 64
#define THREADS 256
#define GPITCH 67                 // 66 cols padded to 67 (conflict-free)
#define GPLANE (10*GPITCH)        // 670 floats per g-plane
#define NPL 12                    // planes per chunk: 4 x-channels x 3 bases
#define NCHUNKS 8
#define WCH_ULL (NPL*9*32)        // 3456 duplicated weights per chunk
#define SMEM_BYTES (NPL*GPLANE*4 + WCH_ULL*8)   // 32160 + 27648 = 59808

typedef unsigned long long ull;

// ---------------- device globals (scratch) ----------------
__device__ float g_gate[NB*NC];
__device__ float g_scale[NB];
__device__ float g_bias[NC*9];   // [o]: S,R0,R2,C0,C2,T00,T02,T20,T22
__device__ __align__(16) ull g_wdup[NCHUNKS*WCH_ULL];

// ---------------- helpers ----------------
__device__ __forceinline__ ull pack2(float lo, float hi) {
    ull r; asm("mov.b64 %0, {%1, %2};" : "=l"(r) : "f"(lo), "f"(hi)); return r;
}
__device__ __forceinline__ void unpack2(ull v, float& lo, float& hi) {
    asm("mov.b64 {%0, %1}, %2;" : "=f"(lo), "=f"(hi) : "l"(v));
}
__device__ __forceinline__ void fma2(ull& d, ull a, ull b) {
    asm("fma.rn.f32x2 %0, %1, %2, %3;" : "=l"(d) : "l"(a), "l"(b), "l"(d));
}
__device__ __forceinline__ float silu_f(float z) {
    float e = __expf(-z);
    return __fdividef(z, 1.0f + e);
}
__device__ __forceinline__ float fast_tanh(float x) {
    float e = __expf(2.0f * x);            // inf for large x is fine
    return 1.0f - __fdividef(2.0f, e + 1.0f);
}

// ---------------- kernel 1: gate_x = mean(x, H, W) ----------------
__global__ void k_gate_mean(const float* __restrict__ x) {
    int plane = blockIdx.x;
    const float* p = x + (size_t)plane * HWSZ;
    float s = 0.f;
    for (int i = threadIdx.x; i < HWSZ; i += 256) s += p[i];
    __shared__ float red[256];
    red[threadIdx.x] = s;
    __syncthreads();
    for (int off = 128; off > 0; off >>= 1) {
        if (threadIdx.x < off) red[threadIdx.x] += red[threadIdx.x + off];
        __syncthreads();
    }
    if (threadIdx.x == 0) g_gate[plane] = red[0] * (1.0f / (float)HWSZ);
}

// ---------------- kernel 2: gating ----------------
__device__ __forceinline__ float cv2_8(const float* v) {
    float m = 0.f;
    for (int i = 0; i < 8; ++i) m += v[i];
    m *= 0.125f;
    float var = 0.f;
    for (int i = 0; i < 8; ++i) { float d = v[i] - m; var += d * d; }
    var *= (1.0f / 7.0f);
    return var / (m * m + 1e-10f);
}

__global__ void k_gating(const float* __restrict__ wg, float* __restrict__ loss_out) {
    __shared__ float sgates[NB][NE];
    int n = threadIdx.x;
    if (n < NB) {
        float logit[NE];
        #pragma unroll
        for (int e = 0; e < NE; ++e) logit[e] = 0.f;
        for (int c = 0; c < NC; ++c) {
            float gx = g_gate[n * NC + c];
            #pragma unroll
            for (int e = 0; e < NE; ++e) logit[e] += gx * wg[c * NE + e];
        }
        float mx = logit[0];
        #pragma unroll
        for (int e = 1; e < NE; ++e) mx = fmaxf(mx, logit[e]);
        float pr[NE]; float se = 0.f;
        #pragma unroll
        for (int e = 0; e < NE; ++e) { pr[e] = __expf(logit[e] - mx); se += pr[e]; }
        float inv = 1.0f / se;
        #pragma unroll
        for (int e = 0; e < NE; ++e) pr[e] *= inv;
        int i0 = 0;
        #pragma unroll
        for (int e = 1; e < NE; ++e) if (pr[e] > pr[i0]) i0 = e;
        int i1 = (i0 == 0) ? 1 : 0;
        #pragma unroll
        for (int e = 0; e < NE; ++e) if (e != i0 && pr[e] > pr[i1]) i1 = e;
        float v0 = pr[i0], v1 = pr[i1];
        float denom = v0 + v1 + 1e-6f;
        #pragma unroll
        for (int e = 0; e < NE; ++e) sgates[n][e] = 0.f;
        sgates[n][i0] = v0 / denom;
        sgates[n][i1] = v1 / denom;
        g_scale[n] = (v0 + v1) / denom;
    }
    __syncthreads();
    if (threadIdx.x == 0) {
        float imp[NE], ld[NE];
        #pragma unroll
        for (int e = 0; e < NE; ++e) { imp[e] = 0.f; ld[e] = 0.f; }
        for (int b = 0; b < NB; ++b)
            for (int e = 0; e < NE; ++e) {
                float v = sgates[b][e];
                imp[e] += v;
                if (v > 0.f) ld[e] += 1.f;
            }
        *loss_out = 0.01f * (cv2_8(imp) + cv2_8(ld));
    }
}

// ---------------- kernel 3a: duplicated weight layout (bases 1..3 only) ----
// layout [cb][plane][tap][o], plane = c4*3 + bi, gi = (bi+1)*32 + cb*4 + c4
__global__ void k_wdup(const float* __restrict__ pw) {
    int idx = blockIdx.x * 256 + threadIdx.x;       // < 27648
    int o  = idx & 31;
    int k  = (idx >> 5) % 9;
    int t  = (idx >> 5) / 9;                        // 0..95 == cb*12 + plane
    int plane = t % 12;
    int cb = t / 12;
    int c4 = plane / 3;
    int bi = plane % 3;
    int gi = (bi + 1) * 32 + cb * 4 + c4;
    float w = pw[(size_t)o * (128 * 9) + gi * 9 + k];
    g_wdup[idx] = pack2(w, w);
}

// ---------------- kernel 3b: P0 bias tables ----------------
__global__ void k_bias(const float* __restrict__ pw) {
    int o = threadIdx.x;
    if (o >= 32) return;
    const float G0 = 0.7310585786300049f;   // silu(1)
    float T[9];
    #pragma unroll
    for (int k = 0; k < 9; ++k) T[k] = 0.f;
    for (int c = 0; c < 32; ++c)
        #pragma unroll
        for (int k = 0; k < 9; ++k) T[k] += pw[(size_t)o * (128 * 9) + c * 9 + k];
    #pragma unroll
    for (int k = 0; k < 9; ++k) T[k] *= G0;
    float S = 0.f;
    #pragma unroll
    for (int k = 0; k < 9; ++k) S += T[k];
    g_bias[o * 9 + 0] = S;
    g_bias[o * 9 + 1] = T[0] + T[1] + T[2];   // R0 (ky=0 row)
    g_bias[o * 9 + 2] = T[6] + T[7] + T[8];   // R2 (ky=2 row)
    g_bias[o * 9 + 3] = T[0] + T[3] + T[6];   // C0 (kx=0 col)
    g_bias[o * 9 + 4] = T[2] + T[5] + T[8];   // C2 (kx=2 col)
    g_bias[o * 9 + 5] = T[0];                 // T00
    g_bias[o * 9 + 6] = T[2];                 // T02
    g_bias[o * 9 + 7] = T[6];                 // T20
    g_bias[o * 9 + 8] = T[8];                 // T22
}

// ---------------- kernel 4: fused basis + conv + bias + scale ----------------
__global__ void __launch_bounds__(THREADS, 2)
k_moe_conv(const float* __restrict__ x, const float* __restrict__ betaw,
           float* __restrict__ y) {
    extern __shared__ float smem[];
    float* gs = smem;                                  // NPL * GPLANE floats
    ull* ws = (ull*)(smem + NPL * GPLANE);

    const int n  = blockIdx.z;
    const int y0 = blockIdx.y * TH;
    const int x0 = blockIdx.x * TW;
    const int tid = threadIdx.x;
    const int og  = tid >> 6;          // 0..3
    const int pt  = tid & 63;
    const int row = pt >> 3;           // 0..7
    const int q   = pt & 7;            // 0..7
    const int col0 = q * 4;
    const int og8  = og * 8;

    const float B2 = 2.25f * betaw[1];
    const float B3 = (100.0f / 3.0f) * betaw[2];

    ull acc[32];
    #pragma unroll
    for (int i = 0; i < 32; ++i) acc[i] = 0ull;

    const float* xn = x + (size_t)n * NC * HWSZ;

    for (int cb = 0; cb < NCHUNKS; ++cb) {
        __syncthreads();
        // ---- stage duplicated weights for this chunk ----
        {
            const uint4* src = (const uint4*)(g_wdup + cb * WCH_ULL);
            uint4* dst = (uint4*)ws;
            for (int i = tid; i < WCH_ULL / 2; i += THREADS)
                dst[i] = src[i];
        }
        // ---- stage g tile: 4 x-channels x 3 bases x 10 rows x 66 cols ----
        for (int idx = tid; idx < 4 * 660; idx += THREADS) {
            int c4  = idx / 660;
            int rem = idx - c4 * 660;
            int r   = rem / 66;
            int cc  = rem - r * 66;
            int gy = y0 - 1 + r;
            int gx = x0 - 1 + cc;
            float g1, g2, g3;
            if ((unsigned)gy < (unsigned)NH && (unsigned)gx < (unsigned)NW) {
                float xv = xn[(size_t)(cb * 4 + c4) * HWSZ + gy * NW + gx];
                float t  = fast_tanh(xv);
                float P2 = t * t - B2;
                float P3 = t * P2 - B3 * t;
                g1 = silu_f(t);
                g2 = silu_f(P2);
                g3 = silu_f(P3);
            } else {
                g1 = g2 = g3 = 0.f;
            }
            int base = r * GPITCH + cc;
            gs[(c4 * 3 + 0) * GPLANE + base] = g1;
            gs[(c4 * 3 + 1) * GPLANE + base] = g2;
            gs[(c4 * 3 + 2) * GPLANE + base] = g3;
        }
        __syncthreads();
        // ---- register-tiled f32x2 GEMM: 12 planes x 9 taps ----
        #pragma unroll 1
        for (int ch = 0; ch < NPL; ++ch) {
            const ull* wp = ws + ch * (9 * 32) + og8;
            const float* gb = gs + ch * GPLANE + row * GPITCH + col0;
            #pragma unroll
            for (int ky = 0; ky < 3; ++ky) {
                const float* gr = gb + ky * GPITCH;
                float a0 = gr[0],  a1 = gr[1],  a2 = gr[2],
                      a3 = gr[3],  a4 = gr[4],  a5 = gr[5];
                float b0 = gr[32], b1 = gr[33], b2 = gr[34],
                      b3 = gr[35], b4 = gr[36], b5 = gr[37];
                ull pa0 = pack2(a0, a1), pa1 = pack2(a1, a2), pa2 = pack2(a2, a3),
                    pa3 = pack2(a3, a4), pa4 = pack2(a4, a5);
                ull pb0 = pack2(b0, b1), pb1 = pack2(b1, b2), pb2 = pack2(b2, b3),
                    pb3 = pack2(b3, b4), pb4 = pack2(b4, b5);
                #pragma unroll
                for (int kx = 0; kx < 3; ++kx) {
                    ull gA = (kx == 0) ? pa0 : (kx == 1) ? pa1 : pa2;
                    ull gB = (kx == 0) ? pa2 : (kx == 1) ? pa3 : pa4;
                    ull gC = (kx == 0) ? pb0 : (kx == 1) ? pb1 : pb2;
                    ull gD = (kx == 0) ? pb2 : (kx == 1) ? pb3 : pb4;
                    const ull* w = wp + (ky * 3 + kx) * 32;
                    ulonglong2 w01 = *(const ulonglong2*)(w + 0);
                    ulonglong2 w23 = *(const ulonglong2*)(w + 2);
                    ulonglong2 w45 = *(const ulonglong2*)(w + 4);
                    ulonglong2 w67 = *(const ulonglong2*)(w + 6);
                    fma2(acc[0],  w01.x, gA); fma2(acc[1],  w01.x, gB);
                    fma2(acc[2],  w01.x, gC); fma2(acc[3],  w01.x, gD);
                    fma2(acc[4],  w01.y, gA); fma2(acc[5],  w01.y, gB);
                    fma2(acc[6],  w01.y, gC); fma2(acc[7],  w01.y, gD);
                    fma2(acc[8],  w23.x, gA); fma2(acc[9],  w23.x, gB);
                    fma2(acc[10], w23.x, gC); fma2(acc[11], w23.x, gD);
                    fma2(acc[12], w23.y, gA); fma2(acc[13], w23.y, gB);
                    fma2(acc[14], w23.y, gC); fma2(acc[15], w23.y, gD);
                    fma2(acc[16], w45.x, gA); fma2(acc[17], w45.x, gB);
                    fma2(acc[18], w45.x, gC); fma2(acc[19], w45.x, gD);
                    fma2(acc[20], w45.y, gA); fma2(acc[21], w45.y, gB);
                    fma2(acc[22], w45.y, gC); fma2(acc[23], w45.y, gD);
                    fma2(acc[24], w67.x, gA); fma2(acc[25], w67.x, gB);
                    fma2(acc[26], w67.x, gC); fma2(acc[27], w67.x, gD);
                    fma2(acc[28], w67.y, gA); fma2(acc[29], w67.y, gB);
                    fma2(acc[30], w67.y, gC); fma2(acc[31], w67.y, gD);
                }
            }
        }
    }

    // ---- epilogue: P0 bias + per-batch gate scale + store ----
    float s = g_scale[n];
    int gy = y0 + row;
    bool top = (gy == 0), bot = (gy == NH - 1);
    #pragma unroll
    for (int o = 0; o < 8; ++o) {
        const float* bt = g_bias + (og8 + o) * 9;
        float S  = bt[0];
        float bbase = S - (top ? bt[1] : 0.f) - (bot ? bt[2] : 0.f);
        float C0 = bt[3], C2 = bt[4];
        float T00 = bt[5], T02 = bt[6], T20 = bt[7], T22 = bt[8];
        #pragma unroll
        for (int h = 0; h < 2; ++h) {
            int gx0 = x0 + col0 + h * 32;
            float bl = bbase, br = bbase;
            if (gx0 == 0)
                bl += -C0 + (top ? T00 : 0.f) + (bot ? T20 : 0.f);
            if (gx0 + 3 == NW - 1)
                br += -C2 + (top ? T02 : 0.f) + (bot ? T22 : 0.f);
            float v0, v1, v2, v3;
            unpack2(acc[o * 4 + 2 * h],     v0, v1);
            unpack2(acc[o * 4 + 2 * h + 1], v2, v3);
            float4 out;
            out.x = (v0 + bl)    * s;
            out.y = (v1 + bbase) * s;
            out.z = (v2 + bbase) * s;
            out.w = (v3 + br)    * s;
            size_t off = ((size_t)(n * NC + og8 + o) * NH + gy) * NW + gx0;
            *(float4*)(y + off) = out;
        }
    }
}

// ---------------- launcher ----------------
extern "C" void kernel_launch(void* const* d_in, const int* in_sizes, int n_in,
                              void* d_out, int out_size) {
    const float* x  = (const float*)d_in[0];
    const float* wg = (const float*)d_in[1];
    const float* pw = (const float*)d_in[2];
    const float* bw = (const float*)d_in[3];
    float* out = (float*)d_out;

    cudaFuncSetAttribute(k_moe_conv, cudaFuncAttributeMaxDynamicSharedMemorySize, SMEM_BYTES);

    k_gate_mean<<<NB * NC, 256>>>(x);
    k_gating<<<1, 32>>>(wg, out + (out_size - 1));
    k_wdup<<<NCHUNKS * WCH_ULL / 256, 256>>>(pw);
    k_bias<<<1, 32>>>(pw);
    dim3 grid(NW / TW, NH / TH, NB);
    k_moe_conv<<<grid, THREADS, SMEM_BYTES>>>(x, bw, out);
}